// round 3
// baseline (speedup 1.0000x reference)
#include <cuda_runtime.h>
#include <cuda_bf16.h>

#define B_   2
#define C_   256
#define N_   4096
#define R_   8
#define G_   4
#define CG_  64      // C/G
#define DIRS 2

// ---------------- scratch (device globals; no allocations allowed) ----------
__device__ float g_q[DIRS][B_][R_][N_];              //  1 MB
__device__ float g_k[DIRS][B_][R_][N_];              //  1 MB
__device__ float g_v[DIRS][B_][C_][N_];              // 16.8 MB
__device__ float g_rS[DIRS][B_][N_];                 // 64 KB (stores 1/S)
__device__ __nv_bfloat16 g_E[DIRS][B_][N_][N_];      // 134 MB

// ---------------- K1: fused low-rank projections qL,kU,qU,kL ----------------
__global__ void k_qkproj(const float* __restrict__ fL, const float* __restrict__ fU,
                         const float* __restrict__ qLw, const float* __restrict__ qLb,
                         const float* __restrict__ kUw, const float* __restrict__ kUb,
                         const float* __restrict__ qUw, const float* __restrict__ qUb,
                         const float* __restrict__ kLw, const float* __restrict__ kLb) {
    __shared__ float w[4][R_][C_];   // 32 KB
    int t = threadIdx.x;             // 256
    int n = blockIdx.x * 256 + t;
    int b = blockIdx.y;
    float* wf = &w[0][0][0];
    for (int i = t; i < R_ * C_; i += 256) {
        wf[i]              = qLw[i];
        wf[2048 + i]       = kUw[i];
        wf[2 * 2048 + i]   = qUw[i];
        wf[3 * 2048 + i]   = kLw[i];
    }
    __syncthreads();
    float aQL[R_], aKU[R_], aQU[R_], aKL[R_];
#pragma unroll
    for (int r = 0; r < R_; r++) { aQL[r] = 0.f; aKU[r] = 0.f; aQU[r] = 0.f; aKL[r] = 0.f; }
    const float* xl = fL + (size_t)b * C_ * N_ + n;
    const float* xu = fU + (size_t)b * C_ * N_ + n;
    for (int c = 0; c < C_; c++) {
        float vl = xl[(size_t)c * N_];
        float vu = xu[(size_t)c * N_];
#pragma unroll
        for (int r = 0; r < R_; r++) {
            aQL[r] = fmaf(w[0][r][c], vl, aQL[r]);
            aKU[r] = fmaf(w[1][r][c], vu, aKU[r]);
            aQU[r] = fmaf(w[2][r][c], vu, aQU[r]);
            aKL[r] = fmaf(w[3][r][c], vl, aKL[r]);
        }
    }
#pragma unroll
    for (int r = 0; r < R_; r++) {
        g_q[0][b][r][n] = aQL[r] + qLb[r];
        g_k[0][b][r][n] = aKU[r] + kUb[r];
        g_q[1][b][r][n] = aQU[r] + qUb[r];
        g_k[1][b][r][n] = aKL[r] + kLb[r];
    }
}

// ---------------- K2: grouped 1x1 convs vU (dir0 from fU), vL (dir1 from fL) -
__global__ void k_vconv(const float* __restrict__ fL, const float* __restrict__ fU,
                        const float* __restrict__ vUw, const float* __restrict__ vUb,
                        const float* __restrict__ vLw, const float* __restrict__ vLb) {
    __shared__ float xs[CG_][128];   // 32 KB
    __shared__ float ws[CG_][CG_];   // 16 KB
    int t  = threadIdx.x;            // 128
    int n0 = blockIdx.x * 128;
    int g  = blockIdx.y;
    int dir = blockIdx.z / B_, b = blockIdx.z % B_;
    const float* x    = dir ? fL  : fU;
    const float* w    = dir ? vLw : vUw;
    const float* bias = dir ? vLb : vUb;
    for (int ci = 0; ci < CG_; ci++)
        xs[ci][t] = x[((size_t)b * C_ + g * CG_ + ci) * N_ + n0 + t];
    for (int i = t; i < CG_ * CG_; i += 128)
        (&ws[0][0])[i] = w[g * CG_ * CG_ + i];
    __syncthreads();
    for (int co = 0; co < CG_; co++) {
        float acc = bias[g * CG_ + co];
#pragma unroll 8
        for (int ci = 0; ci < CG_; ci++)
            acc = fmaf(ws[co][ci], xs[ci][t], acc);
        g_v[dir][b][g * CG_ + co][n0 + t] = acc;
    }
}

// ---------------- K3: E[n,m] = exp(q_n . k_m), bf16, coalesced over m --------
#define EN_TILE 64
__global__ void k_expE() {
    __shared__ float qs[EN_TILE][R_];      // [n][r], 2 KB, float4-readable
    int t  = threadIdx.x;                  // 256
    int m  = blockIdx.x * 256 + t;
    int n0 = blockIdx.y * EN_TILE;
    int dir = blockIdx.z / B_, b = blockIdx.z % B_;
    for (int i = t; i < EN_TILE * R_; i += 256) {
        int nn = i / R_, r = i % R_;
        qs[nn][r] = g_q[dir][b][r][n0 + nn];
    }
    float kr[R_];
#pragma unroll
    for (int r = 0; r < R_; r++) kr[r] = g_k[dir][b][r][m];
    __syncthreads();
#pragma unroll 4
    for (int nn = 0; nn < EN_TILE; nn++) {
        float4 q0 = *(const float4*)&qs[nn][0];
        float4 q1 = *(const float4*)&qs[nn][4];
        float l = q0.x * kr[0] + q0.y * kr[1] + q0.z * kr[2] + q0.w * kr[3]
                + q1.x * kr[4] + q1.y * kr[5] + q1.z * kr[6] + q1.w * kr[7];
        g_E[dir][b][n0 + nn][m] = __float2bfloat16(__expf(l));
    }
}

// ---------------- K3b: rS[n] = 1 / sum_m E[n,m] ------------------------------
__global__ void k_rowsum() {
    __shared__ float red[8];
    int t = threadIdx.x;                   // 256
    int n = blockIdx.x;
    int dir = blockIdx.y / B_, b = blockIdx.y % B_;
    const uint4* rp = (const uint4*)&g_E[dir][b][n][0];
    float s = 0.f;
    for (int i = t; i < N_ / 8; i += 256) {
        uint4 u = rp[i];
        const __nv_bfloat162* p2 = reinterpret_cast<const __nv_bfloat162*>(&u);
#pragma unroll
        for (int j = 0; j < 4; j++)
            s += __bfloat162float(p2[j].x) + __bfloat162float(p2[j].y);
    }
#pragma unroll
    for (int o = 16; o; o >>= 1) s += __shfl_xor_sync(0xffffffffu, s, o);
    if ((t & 31) == 0) red[t >> 5] = s;
    __syncthreads();
    if (t < 8) {
        float v = red[t];
#pragma unroll
        for (int o = 4; o; o >>= 1) v += __shfl_xor_sync(0xffu, v, o);
        if (t == 0) g_rS[dir][b][n] = 1.0f / v;
    }
}

// ---------------- K3c: v'[c,n] = v[c,n] * rS[n] (in place) -------------------
__global__ void k_scaleV() {
    int t = threadIdx.x;                   // 256
    int n = blockIdx.x * 256 + t;
    int c = blockIdx.y;
    int dir = blockIdx.z / B_, b = blockIdx.z % B_;
    g_v[dir][b][c][n] *= g_rS[dir][b][n];
}

// ---------------- K4: OUT = f + beta * (v' @ E)  (SGEMM, 64c x 128m tile) ----
#define TC 64
#define TM 128
#define TK 16
__global__ void __launch_bounds__(256) k_gemm(
        const float* __restrict__ fL, const float* __restrict__ fU,
        const float* __restrict__ beta_p, float* __restrict__ out) {
    __shared__ float As[TK][68];           // [k][c], padded to 68 (16B-aligned rows)
    __shared__ float Bs[TK][TM];           // [k][m]
    int t  = threadIdx.x;                  // 256
    int m0 = blockIdx.x * TM;
    int c0 = blockIdx.y * TC;
    int dir = blockIdx.z / B_, b = blockIdx.z % B_;
    int tc = t >> 4;                       // 0..15 -> c = c0 + tc*4 + i
    int tm = t & 15;                       // 0..15 -> m = m0 + tm*2 + j2*32 + u

    float acc[4][8];
#pragma unroll
    for (int i = 0; i < 4; i++)
#pragma unroll
        for (int j = 0; j < 8; j++) acc[i][j] = 0.f;

    const float* vb = &g_v[dir][b][0][0];
    const __nv_bfloat16* Eb = &g_E[dir][b][0][0];

    int arow = t >> 2;                     // c-row this thread loads (0..63)
    int acol = (t & 3) << 2;               // k-offset (0,4,8,12)
    int brow = t >> 6;                     // 0..3
    int bcol = (t & 63) * 2;               // 0..126

    for (int k0 = 0; k0 < N_; k0 += TK) {
        // A tile: v'[c0..c0+64)[k0..k0+16), store transposed [k][c]
        float4 a4 = *(const float4*)&vb[(size_t)(c0 + arow) * N_ + k0 + acol];
        As[acol + 0][arow] = a4.x;
        As[acol + 1][arow] = a4.y;
        As[acol + 2][arow] = a4.z;
        As[acol + 3][arow] = a4.w;
        // B tile: E[k0..k0+16)[m0..m0+128), bf16 -> f32
#pragma unroll
        for (int i = 0; i < 4; i++) {
            int row = brow + i * 4;
            __nv_bfloat162 e2 = *(const __nv_bfloat162*)&Eb[(size_t)(k0 + row) * N_ + m0 + bcol];
            *(float2*)&Bs[row][bcol] = make_float2(__bfloat162float(e2.x), __bfloat162float(e2.y));
        }
        __syncthreads();
#pragma unroll
        for (int kk = 0; kk < TK; kk++) {
            float4 av = *(const float4*)&As[kk][tc * 4];
            float a[4] = {av.x, av.y, av.z, av.w};
#pragma unroll
            for (int j2 = 0; j2 < 4; j2++) {
                float2 b2 = *(const float2*)&Bs[kk][tm * 2 + j2 * 32];
#pragma unroll
                for (int i = 0; i < 4; i++) {
                    acc[i][j2 * 2]     = fmaf(a[i], b2.x, acc[i][j2 * 2]);
                    acc[i][j2 * 2 + 1] = fmaf(a[i], b2.y, acc[i][j2 * 2 + 1]);
                }
            }
        }
        __syncthreads();
    }

    float beta = *beta_p;
    const float* f = dir ? fU : fL;
    float* o = out + (size_t)dir * B_ * C_ * N_;
#pragma unroll
    for (int i = 0; i < 4; i++) {
        int c = c0 + tc * 4 + i;
        size_t base = ((size_t)b * C_ + c) * N_ + m0;
#pragma unroll
        for (int j2 = 0; j2 < 4; j2++) {
            int m = tm * 2 + j2 * 32;
            float2 fv = *(const float2*)&f[base + m];
            float2 r;
            r.x = fv.x + beta * acc[i][j2 * 2];
            r.y = fv.y + beta * acc[i][j2 * 2 + 1];
            *(float2*)&o[base + m] = r;
        }
    }
}

// ---------------- launch -----------------------------------------------------
extern "C" void kernel_launch(void* const* d_in, const int* in_sizes, int n_in,
                              void* d_out, int out_size) {
    const float* fL  = (const float*)d_in[0];
    const float* fU  = (const float*)d_in[1];
    const float* qLw = (const float*)d_in[2];
    const float* qLb = (const float*)d_in[3];
    const float* kUw = (const float*)d_in[4];
    const float* kUb = (const float*)d_in[5];
    const float* vUw = (const float*)d_in[6];
    const float* vUb = (const float*)d_in[7];
    const float* qUw = (const float*)d_in[8];
    const float* qUb = (const float*)d_in[9];
    const float* kLw = (const float*)d_in[10];
    const float* kLb = (const float*)d_in[11];
    const float* vLw = (const float*)d_in[12];
    const float* vLb = (const float*)d_in[13];
    const float* beta = (const float*)d_in[14];
    float* out = (float*)d_out;

    k_qkproj<<<dim3(N_ / 256, B_), 256>>>(fL, fU, qLw, qLb, kUw, kUb, qUw, qUb, kLw, kLb);
    k_vconv<<<dim3(N_ / 128, G_, DIRS * B_), 128>>>(fL, fU, vUw, vUb, vLw, vLb);
    k_expE<<<dim3(N_ / 256, N_ / EN_TILE, DIRS * B_), 256>>>();
    k_rowsum<<<dim3(N_, DIRS * B_), 256>>>();
    k_scaleV<<<dim3(N_ / 256, C_, DIRS * B_), 256>>>();
    k_gemm<<<dim3(N_ / TM, C_ / TC, DIRS * B_), 256>>>(fL, fU, beta, out);
}

// round 6
// speedup vs baseline: 3.3652x; 3.3652x over previous
#include <cuda_runtime.h>
#include <cuda_bf16.h>
#include <cstdint>

#define B_   2
#define C_   256
#define N_   4096
#define R_   8
#define G_   4
#define CG_  64
#define DB   4        // DIRS*B_

// ---------------- scratch ---------------------------------------------------
__device__ float g_q[DB][R_][N_];
__device__ float g_k[DB][R_][N_];
__device__ float g_v[DB][C_][N_];
__device__ float g_S[DB][N_];
__device__ __nv_bfloat16 g_vb[DB][C_][N_];          // v' in bf16 (A operand)
__device__ __nv_bfloat16 g_E[DB][N_][N_];           // Et[m][n] = exp(q_n . k_m)

// ---------------- helpers ----------------------------------------------------
__device__ __forceinline__ uint32_t smem_u32(const void* p) {
    uint32_t a;
    asm("{ .reg .u64 t; cvta.to.shared.u64 t, %1; cvt.u32.u64 %0, t; }" : "=r"(a) : "l"(p));
    return a;
}
#define SWZ(o) ((o) ^ (((o) >> 3) & 0x70))
#define CPA(s, g) asm volatile("cp.async.cg.shared.global [%0], [%1], 16;" :: "r"(s), "l"(g) : "memory")
#define CPC()     asm volatile("cp.async.commit_group;" ::: "memory")
#define CPW(n)    asm volatile("cp.async.wait_group %0;" :: "n"(n) : "memory")

__device__ __forceinline__ void ldsm4(uint32_t* r, uint32_t addr) {
    asm volatile("ldmatrix.sync.aligned.m8n8.x4.shared.b16 {%0,%1,%2,%3}, [%4];"
                 : "=r"(r[0]), "=r"(r[1]), "=r"(r[2]), "=r"(r[3]) : "r"(addr));
}
__device__ __forceinline__ void mma16816(float* d, const uint32_t* a, uint32_t b0, uint32_t b1) {
    asm volatile("mma.sync.aligned.m16n8k16.row.col.f32.bf16.bf16.f32 "
                 "{%0,%1,%2,%3}, {%4,%5,%6,%7}, {%8,%9}, {%0,%1,%2,%3};"
                 : "+f"(d[0]), "+f"(d[1]), "+f"(d[2]), "+f"(d[3])
                 : "r"(a[0]), "r"(a[1]), "r"(a[2]), "r"(a[3]), "r"(b0), "r"(b1));
}

// ---------------- K1: fused low-rank projections ----------------------------
__global__ void k_qkproj(const float* __restrict__ fL, const float* __restrict__ fU,
                         const float* __restrict__ qLw, const float* __restrict__ qLb,
                         const float* __restrict__ kUw, const float* __restrict__ kUb,
                         const float* __restrict__ qUw, const float* __restrict__ qUb,
                         const float* __restrict__ kLw, const float* __restrict__ kLb) {
    __shared__ float w[4][R_][C_];
    int t = threadIdx.x;
    int n = blockIdx.x * 256 + t;
    int b = blockIdx.y;
    float* wf = &w[0][0][0];
    for (int i = t; i < R_ * C_; i += 256) {
        wf[i] = qLw[i]; wf[2048 + i] = kUw[i]; wf[4096 + i] = qUw[i]; wf[6144 + i] = kLw[i];
    }
    __syncthreads();
    float aQL[R_], aKU[R_], aQU[R_], aKL[R_];
#pragma unroll
    for (int r = 0; r < R_; r++) { aQL[r]=0.f; aKU[r]=0.f; aQU[r]=0.f; aKL[r]=0.f; }
    const float* xl = fL + (size_t)b * C_ * N_ + n;
    const float* xu = fU + (size_t)b * C_ * N_ + n;
    for (int c = 0; c < C_; c++) {
        float vl = xl[(size_t)c * N_];
        float vu = xu[(size_t)c * N_];
#pragma unroll
        for (int r = 0; r < R_; r++) {
            aQL[r] = fmaf(w[0][r][c], vl, aQL[r]);
            aKU[r] = fmaf(w[1][r][c], vu, aKU[r]);
            aQU[r] = fmaf(w[2][r][c], vu, aQU[r]);
            aKL[r] = fmaf(w[3][r][c], vl, aKL[r]);
        }
    }
#pragma unroll
    for (int r = 0; r < R_; r++) {
        g_q[b][r][n]     = aQL[r] + qLb[r];
        g_k[b][r][n]     = aKU[r] + kUb[r];
        g_q[2 + b][r][n] = aQU[r] + qUb[r];
        g_k[2 + b][r][n] = aKL[r] + kLb[r];
    }
}

// ---------------- K2: grouped 1x1 convs -------------------------------------
__global__ void k_vconv(const float* __restrict__ fL, const float* __restrict__ fU,
                        const float* __restrict__ vUw, const float* __restrict__ vUb,
                        const float* __restrict__ vLw, const float* __restrict__ vLb) {
    __shared__ float xs[CG_][128];
    __shared__ float ws[CG_][CG_];
    int t  = threadIdx.x;
    int n0 = blockIdx.x * 128;
    int g  = blockIdx.y;
    int z  = blockIdx.z;
    int dir = z >> 1, b = z & 1;
    const float* x    = dir ? fL  : fU;
    const float* w    = dir ? vLw : vUw;
    const float* bias = dir ? vLb : vUb;
    for (int ci = 0; ci < CG_; ci++)
        xs[ci][t] = x[((size_t)b * C_ + g * CG_ + ci) * N_ + n0 + t];
    for (int i = t; i < CG_ * CG_; i += 128)
        (&ws[0][0])[i] = w[g * CG_ * CG_ + i];
    __syncthreads();
    for (int co = 0; co < CG_; co++) {
        float acc = bias[g * CG_ + co];
#pragma unroll 8
        for (int ci = 0; ci < CG_; ci++)
            acc = fmaf(ws[co][ci], xs[ci][t], acc);
        g_v[z][g * CG_ + co][n0 + t] = acc;
    }
}

// ---------------- K3: Et[m][n] = exp(q_n . k_m), bf16 ------------------------
__global__ void k_expT() {
    __shared__ float qs[64][R_];
    int t  = threadIdx.x;              // 256
    int m  = blockIdx.x * 256 + t;
    int n0 = blockIdx.y * 64;
    int z  = blockIdx.z;
    for (int i = t; i < 64 * R_; i += 256)
        qs[i / R_][i % R_] = g_q[z][i % R_][n0 + i / R_];
    float kr[R_];
#pragma unroll
    for (int r = 0; r < R_; r++) kr[r] = g_k[z][r][m];
    __syncthreads();
    __nv_bfloat162 buf[32];
#pragma unroll 8
    for (int nn = 0; nn < 64; nn += 2) {
        float4 a0 = *(const float4*)&qs[nn][0];
        float4 a1 = *(const float4*)&qs[nn][4];
        float4 b0 = *(const float4*)&qs[nn + 1][0];
        float4 b1 = *(const float4*)&qs[nn + 1][4];
        float l0 = a0.x*kr[0]+a0.y*kr[1]+a0.z*kr[2]+a0.w*kr[3]+a1.x*kr[4]+a1.y*kr[5]+a1.z*kr[6]+a1.w*kr[7];
        float l1 = b0.x*kr[0]+b0.y*kr[1]+b0.z*kr[2]+b0.w*kr[3]+b1.x*kr[4]+b1.y*kr[5]+b1.z*kr[6]+b1.w*kr[7];
        buf[nn >> 1] = __floats2bfloat162_rn(__expf(l0), __expf(l1));
    }
    uint4* dst = (uint4*)&g_E[z][m][n0];
    const uint4* s = (const uint4*)buf;
#pragma unroll
    for (int i = 0; i < 8; i++) dst[i] = s[i];
}

// ---------------- K3b: zero S, column-sum S[n] = sum_m Et[m][n] --------------
__global__ void k_zeroS() {
    ((float*)g_S)[blockIdx.x * 256 + threadIdx.x] = 0.f;
}
__global__ void k_colsum() {
    int t  = threadIdx.x;                         // 256
    int nb = blockIdx.x * 2048 + t * 8;
    int m0 = blockIdx.y * 128;
    int z  = blockIdx.z;
    float s[8] = {0,0,0,0,0,0,0,0};
    for (int m = m0; m < m0 + 128; m++) {
        uint4 u = *(const uint4*)&g_E[z][m][nb];
        const __nv_bfloat162* p = (const __nv_bfloat162*)&u;
#pragma unroll
        for (int j = 0; j < 4; j++) {
            s[2*j]   += __bfloat162float(p[j].x);
            s[2*j+1] += __bfloat162float(p[j].y);
        }
    }
#pragma unroll
    for (int j = 0; j < 8; j++) atomicAdd(&g_S[z][nb + j], s[j]);
}

// ---------------- K3c: v'[c,n] = v[c,n]/S[n] -> bf16 -------------------------
__global__ void k_scaleVb() {
    int t = threadIdx.x;
    int n = blockIdx.x * 256 + t;
    int c = blockIdx.y;
    int z = blockIdx.z;
    float r = 1.0f / g_S[z][n];
    g_vb[z][c][n] = __float2bfloat16(g_v[z][c][n] * r);
}

// ---------------- K4: bf16 mma.sync GEMM  OUT = f + beta * (v' @ Et^T) -------
// CTA tile: 128 c x 128 m, K tiles of 64, cp.async double buffer.
#define KT 64
#define NKT (N_ / KT)
#define GEMM_SMEM (1024 + 2 * 32768)

__global__ void __launch_bounds__(256, 2) k_gemm_mma(
        const float* __restrict__ fL, const float* __restrict__ fU,
        const float* __restrict__ beta_p, float* __restrict__ out) {
    extern __shared__ char dsm[];
    uint32_t sb0 = smem_u32(dsm);
    uint32_t sb = (sb0 + 1023) & ~1023u;

    int t = threadIdx.x, lane = t & 31, wid = t >> 5;
    int m0 = blockIdx.x * 128, c0 = blockIdx.y * 128, z = blockIdx.z;
    int dir = z >> 1, b = z & 1;
    int wc = wid >> 2, wm = wid & 3;                 // warp tile: 64c x 32m

    const __nv_bfloat16* Ab = &g_vb[z][c0][0];
    const __nv_bfloat16* Bb = &g_E[z][m0][0];

    int row  = t >> 3;            // 0..31
    int colb = (t & 7) * 16;      // byte offset within 128B row

    float acc[4][4][4];
#pragma unroll
    for (int i = 0; i < 4; i++)
#pragma unroll
        for (int j = 0; j < 4; j++)
#pragma unroll
            for (int q = 0; q < 4; q++) acc[i][j][q] = 0.f;

    // precomputed (swizzled) ldmatrix base offsets (row-part only varies with i/jj)
    uint32_t aRow = (uint32_t)(wc * 64 + (lane & 15));
    uint32_t aKb  = (uint32_t)((lane >> 4) * 16);
    uint32_t bRow = (uint32_t)(wm * 32 + ((lane >> 4) & 1) * 8 + (lane & 7));
    uint32_t bKb  = (uint32_t)(((lane >> 3) & 1) * 16);

    // prefetch tile 0
    {
        uint32_t base = sb;
        const char* ap = (const char*)Ab + colb;
        const char* bp = (const char*)Bb + colb;
#pragma unroll
        for (int i = 0; i < 4; i++) {
            int r = row + i * 32;
            CPA(base + SWZ(r * 128 + colb), ap + (size_t)r * N_ * 2);
            CPA(base + 16384 + SWZ(r * 128 + colb), bp + (size_t)r * N_ * 2);
        }
        CPC();
    }

    for (int kt = 0; kt < NKT; kt++) {
        if (kt + 1 < NKT) {
            uint32_t base = sb + ((kt + 1) & 1) * 32768;
            size_t kOff = (size_t)(kt + 1) * KT * 2;
            const char* ap = (const char*)Ab + kOff + colb;
            const char* bp = (const char*)Bb + kOff + colb;
#pragma unroll
            for (int i = 0; i < 4; i++) {
                int r = row + i * 32;
                CPA(base + SWZ(r * 128 + colb), ap + (size_t)r * N_ * 2);
                CPA(base + 16384 + SWZ(r * 128 + colb), bp + (size_t)r * N_ * 2);
            }
            CPC();
            CPW(1);
        } else {
            CPW(0);
        }
        __syncthreads();

        uint32_t As = sb + (kt & 1) * 32768;
        uint32_t Bs = As + 16384;
#pragma unroll
        for (int kk = 0; kk < 4; kk++) {
            uint32_t a[4][4], brg[2][4];
#pragma unroll
            for (int i = 0; i < 4; i++)
                ldsm4(a[i], As + SWZ((aRow + i * 16) * 128 + kk * 32 + aKb));
#pragma unroll
            for (int jj = 0; jj < 2; jj++)
                ldsm4(brg[jj], Bs + SWZ((bRow + jj * 16) * 128 + kk * 32 + bKb));
#pragma unroll
            for (int i = 0; i < 4; i++)
#pragma unroll
                for (int j = 0; j < 4; j++)
                    mma16816(acc[i][j], a[i], brg[j >> 1][(j & 1) * 2], brg[j >> 1][(j & 1) * 2 + 1]);
        }
        __syncthreads();
    }

    // epilogue: out = f + beta * acc
    float beta = *beta_p;
    const float* fsrc = dir ? fU : fL;
    float* osrc = out + (size_t)dir * B_ * C_ * N_;
#pragma unroll
    for (int i = 0; i < 4; i++) {
        int cr = c0 + wc * 64 + i * 16 + (lane >> 2);
#pragma unroll
        for (int j = 0; j < 4; j++) {
            int mc = m0 + wm * 32 + j * 8 + (lane & 3) * 2;
            size_t i0 = ((size_t)b * C_ + cr) * N_ + mc;
            size_t i1 = i0 + 8 * (size_t)N_;
            float2 f0 = *(const float2*)&fsrc[i0];
            float2 f1 = *(const float2*)&fsrc[i1];
            float2 d0, d1;
            d0.x = f0.x + beta * acc[i][j][0];
            d0.y = f0.y + beta * acc[i][j][1];
            d1.x = f1.x + beta * acc[i][j][2];
            d1.y = f1.y + beta * acc[i][j][3];
            *(float2*)&osrc[i0] = d0;
            *(float2*)&osrc[i1] = d1;
        }
    }
}

// ---------------- launch -----------------------------------------------------
extern "C" void kernel_launch(void* const* d_in, const int* in_sizes, int n_in,
                              void* d_out, int out_size) {
    const float* fL  = (const float*)d_in[0];
    const float* fU  = (const float*)d_in[1];
    const float* qLw = (const float*)d_in[2];
    const float* qLb = (const float*)d_in[3];
    const float* kUw = (const float*)d_in[4];
    const float* kUb = (const float*)d_in[5];
    const float* vUw = (const float*)d_in[6];
    const float* vUb = (const float*)d_in[7];
    const float* qUw = (const float*)d_in[8];
    const float* qUb = (const float*)d_in[9];
    const float* kLw = (const float*)d_in[10];
    const float* kLb = (const float*)d_in[11];
    const float* vLw = (const float*)d_in[12];
    const float* vLb = (const float*)d_in[13];
    const float* beta = (const float*)d_in[14];
    float* out = (float*)d_out;

    k_qkproj<<<dim3(N_ / 256, B_), 256>>>(fL, fU, qLw, qLb, kUw, kUb, qUw, qUb, kLw, kLb);
    k_vconv<<<dim3(N_ / 128, G_, DB), 128>>>(fL, fU, vUw, vUb, vLw, vLb);
    k_zeroS<<<DB * N_ / 256, 256>>>();
    k_expT<<<dim3(N_ / 256, N_ / 64, DB), 256>>>();
    k_colsum<<<dim3(N_ / 2048, N_ / 128, DB), 256>>>();
    k_scaleVb<<<dim3(N_ / 256, C_, DB), 256>>>();
    cudaFuncSetAttribute(k_gemm_mma, cudaFuncAttributeMaxDynamicSharedMemorySize, GEMM_SMEM);
    k_gemm_mma<<<dim3(N_ / 128, C_ / 128, DB), 256, GEMM_SMEM>>>(fL, fU, beta, out);
}

// round 9
// speedup vs baseline: 4.0529x; 1.2044x over previous
#include <cuda_runtime.h>
#include <cuda_bf16.h>
#include <cstdint>

#define B_   2
#define C_   256
#define N_   4096
#define R_   8
#define G_   4
#define CG_  64
#define DB   4        // DIRS*B_

// ---------------- scratch ---------------------------------------------------
__device__ float g_q[DB][R_][N_];
__device__ float g_k[DB][R_][N_];
__device__ float g_v[DB][C_][N_];
__device__ float g_S[DB][N_];
__device__ __nv_bfloat16 g_vb[DB][C_][N_];          // v' in bf16 (A operand)
__device__ __nv_bfloat16 g_E[DB][N_][N_];           // Et[m][n] = exp(q_n . k_m)

// ---------------- helpers ----------------------------------------------------
__device__ __forceinline__ uint32_t smem_u32(const void* p) {
    uint32_t a;
    asm("{ .reg .u64 t; cvta.to.shared.u64 t, %1; cvt.u32.u64 %0, t; }" : "=r"(a) : "l"(p));
    return a;
}
#define SWZ(o) ((o) ^ (((o) >> 3) & 0x70))
#define CPA(s, g) asm volatile("cp.async.cg.shared.global [%0], [%1], 16;" :: "r"(s), "l"(g) : "memory")
#define CPC()     asm volatile("cp.async.commit_group;" ::: "memory")
#define CPW(n)    asm volatile("cp.async.wait_group %0;" :: "n"(n) : "memory")

__device__ __forceinline__ void ldsm4(uint32_t* r, uint32_t addr) {
    asm volatile("ldmatrix.sync.aligned.m8n8.x4.shared.b16 {%0,%1,%2,%3}, [%4];"
                 : "=r"(r[0]), "=r"(r[1]), "=r"(r[2]), "=r"(r[3]) : "r"(addr));
}
__device__ __forceinline__ void mma16816(float* d, const uint32_t* a, uint32_t b0, uint32_t b1) {
    asm volatile("mma.sync.aligned.m16n8k16.row.col.f32.bf16.bf16.f32 "
                 "{%0,%1,%2,%3}, {%4,%5,%6,%7}, {%8,%9}, {%0,%1,%2,%3};"
                 : "+f"(d[0]), "+f"(d[1]), "+f"(d[2]), "+f"(d[3])
                 : "r"(a[0]), "r"(a[1]), "r"(a[2]), "r"(a[3]), "r"(b0), "r"(b1));
}

// ---------------- K1: fused low-rank projections (4 c-slices per block) ------
// block: 256 thr = 4 slices x 64 n.  grid: (N_/64, B_) = 128 CTAs.
__global__ void k_qkproj(const float* __restrict__ fL, const float* __restrict__ fU,
                         const float* __restrict__ qLw, const float* __restrict__ qLb,
                         const float* __restrict__ kUw, const float* __restrict__ kUb,
                         const float* __restrict__ qUw, const float* __restrict__ qUb,
                         const float* __restrict__ kLw, const float* __restrict__ kLb) {
    __shared__ float sbuf[8448];     // 33 KB: weights (8192 f) then partials (8448 f)
    int t = threadIdx.x;
    int n0 = blockIdx.x * 64;
    int b  = blockIdx.y;
    int nl = t & 63, slice = t >> 6;

    for (int i = t; i < R_ * C_; i += 256) {
        sbuf[i] = qLw[i]; sbuf[2048 + i] = kUw[i]; sbuf[4096 + i] = qUw[i]; sbuf[6144 + i] = kLw[i];
    }
    __syncthreads();

    float aQL[R_], aKU[R_], aQU[R_], aKL[R_];
#pragma unroll
    for (int r = 0; r < R_; r++) { aQL[r]=0.f; aKU[r]=0.f; aQU[r]=0.f; aKL[r]=0.f; }
    const float* xl = fL + (size_t)b * C_ * N_ + n0 + nl;
    const float* xu = fU + (size_t)b * C_ * N_ + n0 + nl;
    for (int ci = 0; ci < 64; ci++) {
        int c = slice * 64 + ci;
        float vl = xl[(size_t)c * N_];
        float vu = xu[(size_t)c * N_];
#pragma unroll
        for (int r = 0; r < R_; r++) {
            aQL[r] = fmaf(sbuf[r * 256 + c], vl, aQL[r]);
            aKU[r] = fmaf(sbuf[2048 + r * 256 + c], vu, aKU[r]);
            aQU[r] = fmaf(sbuf[4096 + r * 256 + c], vu, aQU[r]);
            aKL[r] = fmaf(sbuf[6144 + r * 256 + c], vl, aKL[r]);
        }
    }
    __syncthreads();                 // weights no longer needed; overlay partials
    {
        float* red = &sbuf[(size_t)(slice * 64 + nl) * 33];
#pragma unroll
        for (int r = 0; r < R_; r++) {
            red[r] = aQL[r]; red[8 + r] = aKU[r]; red[16 + r] = aQU[r]; red[24 + r] = aKL[r];
        }
    }
    __syncthreads();
    {
        int n2 = t & 63, grp = t >> 6;
#pragma unroll
        for (int j = 0; j < R_; j++) {
            int o = grp * 8 + j;
            float s = sbuf[(0 * 64 + n2) * 33 + o] + sbuf[(1 * 64 + n2) * 33 + o]
                    + sbuf[(2 * 64 + n2) * 33 + o] + sbuf[(3 * 64 + n2) * 33 + o];
            int n = n0 + n2;
            if (grp == 0)      g_q[b][j][n]     = s + qLb[j];
            else if (grp == 1) g_k[b][j][n]     = s + kUb[j];
            else if (grp == 2) g_q[2 + b][j][n] = s + qUb[j];
            else               g_k[2 + b][j][n] = s + kLb[j];
        }
    }
}

// ---------------- K2: grouped 1x1 convs -------------------------------------
__global__ void k_vconv(const float* __restrict__ fL, const float* __restrict__ fU,
                        const float* __restrict__ vUw, const float* __restrict__ vUb,
                        const float* __restrict__ vLw, const float* __restrict__ vLb) {
    __shared__ float xs[CG_][128];
    __shared__ float ws[CG_][CG_];
    int t  = threadIdx.x;
    int n0 = blockIdx.x * 128;
    int g  = blockIdx.y;
    int z  = blockIdx.z;
    int dir = z >> 1, b = z & 1;
    const float* x    = dir ? fL  : fU;
    const float* w    = dir ? vLw : vUw;
    const float* bias = dir ? vLb : vUb;
    for (int ci = 0; ci < CG_; ci++)
        xs[ci][t] = x[((size_t)b * C_ + g * CG_ + ci) * N_ + n0 + t];
    for (int i = t; i < CG_ * CG_; i += 128)
        (&ws[0][0])[i] = w[g * CG_ * CG_ + i];
    __syncthreads();
    for (int co = 0; co < CG_; co++) {
        float acc = bias[g * CG_ + co];
#pragma unroll 8
        for (int ci = 0; ci < CG_; ci++)
            acc = fmaf(ws[co][ci], xs[ci][t], acc);
        g_v[z][g * CG_ + co][n0 + t] = acc;
    }
}

// ---------------- K3: Et[m][n]=exp(q_n.k_m) bf16, coalesced + fused S sum ----
// block 256 thr: 8 warps x 8 m-rows each; lane -> 8 consecutive n.
// tile: 64 m x 256 n.  grid (N_/64, N_/256, DB).
__global__ void __launch_bounds__(256) k_expT() {
    __shared__ float ks[64][9];        // k[m][r], padded
    __shared__ float sacc[8][256];     // per-warp partial column sums
    int t = threadIdx.x, lane = t & 31, w = t >> 5;
    int m0 = blockIdx.x * 64;
    int n0 = blockIdx.y * 256;
    int z  = blockIdx.z;

    for (int i = t; i < 64 * R_; i += 256)
        ks[i >> 3][i & 7] = g_k[z][i & 7][m0 + (i >> 3)];

    // q for this thread's 8 n values, all 8 ranks, in registers
    float qr[R_][8];
#pragma unroll
    for (int r = 0; r < R_; r++) {
        float4 q0 = *(const float4*)&g_q[z][r][n0 + lane * 8];
        float4 q1 = *(const float4*)&g_q[z][r][n0 + lane * 8 + 4];
        qr[r][0]=q0.x; qr[r][1]=q0.y; qr[r][2]=q0.z; qr[r][3]=q0.w;
        qr[r][4]=q1.x; qr[r][5]=q1.y; qr[r][6]=q1.z; qr[r][7]=q1.w;
    }
    __syncthreads();

    float s[8] = {0,0,0,0,0,0,0,0};
#pragma unroll
    for (int mi = 0; mi < 8; mi++) {
        int mrow = w * 8 + mi;
        float km[R_];
#pragma unroll
        for (int r = 0; r < R_; r++) km[r] = ks[mrow][r];   // broadcast
        float e[8];
#pragma unroll
        for (int j = 0; j < 8; j++) {
            float l = qr[0][j]*km[0] + qr[1][j]*km[1] + qr[2][j]*km[2] + qr[3][j]*km[3]
                    + qr[4][j]*km[4] + qr[5][j]*km[5] + qr[6][j]*km[6] + qr[7][j]*km[7];
            e[j] = __expf(l);
            s[j] += e[j];
        }
        __nv_bfloat162 buf[4];
#pragma unroll
        for (int j = 0; j < 4; j++)
            buf[j] = __floats2bfloat162_rn(e[2*j], e[2*j+1]);
        *(uint4*)&g_E[z][m0 + mrow][n0 + lane * 8] = *(const uint4*)buf;  // warp: 512B contiguous
    }
#pragma unroll
    for (int j = 0; j < 8; j++) sacc[w][lane * 8 + j] = s[j];
    __syncthreads();
    float tot = sacc[0][t] + sacc[1][t] + sacc[2][t] + sacc[3][t]
              + sacc[4][t] + sacc[5][t] + sacc[6][t] + sacc[7][t];
    atomicAdd(&g_S[z][n0 + t], tot);
}

__global__ void k_zeroS() {
    ((float*)g_S)[blockIdx.x * 256 + threadIdx.x] = 0.f;
}

// ---------------- K3c: v'[c,n] = v[c,n]/S[n] -> bf16 (vectorized) ------------
__global__ void k_scaleVb() {
    int n4 = (blockIdx.x * 256 + threadIdx.x) * 4;
    int c = blockIdx.y;
    int z = blockIdx.z;
    float4 v = *(const float4*)&g_v[z][c][n4];
    float4 sv = *(const float4*)&g_S[z][n4];
    __nv_bfloat162 o[2];
    o[0] = __floats2bfloat162_rn(v.x / sv.x, v.y / sv.y);
    o[1] = __floats2bfloat162_rn(v.z / sv.z, v.w / sv.w);
    *(uint2*)&g_vb[z][c][n4] = *(const uint2*)o;
}

// ---------------- K4: bf16 mma.sync GEMM  OUT = f + beta * (v' @ Et^T) -------
#define KT 64
#define NKT (N_ / KT)
#define GEMM_SMEM (1024 + 2 * 32768)

__global__ void __launch_bounds__(256, 2) k_gemm_mma(
        const float* __restrict__ fL, const float* __restrict__ fU,
        const float* __restrict__ beta_p, float* __restrict__ out) {
    extern __shared__ char dsm[];
    uint32_t sb0 = smem_u32(dsm);
    uint32_t sb = (sb0 + 1023) & ~1023u;

    int t = threadIdx.x, lane = t & 31, wid = t >> 5;
    int m0 = blockIdx.x * 128, c0 = blockIdx.y * 128, z = blockIdx.z;
    int dir = z >> 1, b = z & 1;
    int wc = wid >> 2, wm = wid & 3;                 // warp tile: 64c x 32m

    const __nv_bfloat16* Ab = &g_vb[z][c0][0];
    const __nv_bfloat16* Bb = &g_E[z][m0][0];

    int row  = t >> 3;
    int colb = (t & 7) * 16;

    float acc[4][4][4];
#pragma unroll
    for (int i = 0; i < 4; i++)
#pragma unroll
        for (int j = 0; j < 4; j++)
#pragma unroll
            for (int q = 0; q < 4; q++) acc[i][j][q] = 0.f;

    uint32_t aRow = (uint32_t)(wc * 64 + (lane & 15));
    uint32_t aKb  = (uint32_t)((lane >> 4) * 16);
    uint32_t bRow = (uint32_t)(wm * 32 + ((lane >> 4) & 1) * 8 + (lane & 7));
    uint32_t bKb  = (uint32_t)(((lane >> 3) & 1) * 16);

    {
        uint32_t base = sb;
        const char* ap = (const char*)Ab + colb;
        const char* bp = (const char*)Bb + colb;
#pragma unroll
        for (int i = 0; i < 4; i++) {
            int r = row + i * 32;
            CPA(base + SWZ(r * 128 + colb), ap + (size_t)r * N_ * 2);
            CPA(base + 16384 + SWZ(r * 128 + colb), bp + (size_t)r * N_ * 2);
        }
        CPC();
    }

    for (int kt = 0; kt < NKT; kt++) {
        if (kt + 1 < NKT) {
            uint32_t base = sb + ((kt + 1) & 1) * 32768;
            size_t kOff = (size_t)(kt + 1) * KT * 2;
            const char* ap = (const char*)Ab + kOff + colb;
            const char* bp = (const char*)Bb + kOff + colb;
#pragma unroll
            for (int i = 0; i < 4; i++) {
                int r = row + i * 32;
                CPA(base + SWZ(r * 128 + colb), ap + (size_t)r * N_ * 2);
                CPA(base + 16384 + SWZ(r * 128 + colb), bp + (size_t)r * N_ * 2);
            }
            CPC();
            CPW(1);
        } else {
            CPW(0);
        }
        __syncthreads();

        uint32_t As = sb + (kt & 1) * 32768;
        uint32_t Bs = As + 16384;
#pragma unroll
        for (int kk = 0; kk < 4; kk++) {
            uint32_t a[4][4], brg[2][4];
#pragma unroll
            for (int i = 0; i < 4; i++)
                ldsm4(a[i], As + SWZ((aRow + i * 16) * 128 + kk * 32 + aKb));
#pragma unroll
            for (int jj = 0; jj < 2; jj++)
                ldsm4(brg[jj], Bs + SWZ((bRow + jj * 16) * 128 + kk * 32 + bKb));
#pragma unroll
            for (int i = 0; i < 4; i++)
#pragma unroll
                for (int j = 0; j < 4; j++)
                    mma16816(acc[i][j], a[i], brg[j >> 1][(j & 1) * 2], brg[j >> 1][(j & 1) * 2 + 1]);
        }
        __syncthreads();
    }

    float beta = *beta_p;
    const float* fsrc = dir ? fU : fL;
    float* osrc = out + (size_t)dir * B_ * C_ * N_;
#pragma unroll
    for (int i = 0; i < 4; i++) {
        int cr = c0 + wc * 64 + i * 16 + (lane >> 2);
#pragma unroll
        for (int j = 0; j < 4; j++) {
            int mc = m0 + wm * 32 + j * 8 + (lane & 3) * 2;
            size_t i0 = ((size_t)b * C_ + cr) * N_ + mc;
            size_t i1 = i0 + 8 * (size_t)N_;
            float2 f0 = *(const float2*)&fsrc[i0];
            float2 f1 = *(const float2*)&fsrc[i1];
            float2 d0, d1;
            d0.x = f0.x + beta * acc[i][j][0];
            d0.y = f0.y + beta * acc[i][j][1];
            d1.x = f1.x + beta * acc[i][j][2];
            d1.y = f1.y + beta * acc[i][j][3];
            *(float2*)&osrc[i0] = d0;
            *(float2*)&osrc[i1] = d1;
        }
    }
}

// ---------------- launch -----------------------------------------------------
extern "C" void kernel_launch(void* const* d_in, const int* in_sizes, int n_in,
                              void* d_out, int out_size) {
    const float* fL  = (const float*)d_in[0];
    const float* fU  = (const float*)d_in[1];
    const float* qLw = (const float*)d_in[2];
    const float* qLb = (const float*)d_in[3];
    const float* kUw = (const float*)d_in[4];
    const float* kUb = (const float*)d_in[5];
    const float* vUw = (const float*)d_in[6];
    const float* vUb = (const float*)d_in[7];
    const float* qUw = (const float*)d_in[8];
    const float* qUb = (const float*)d_in[9];
    const float* kLw = (const float*)d_in[10];
    const float* kLb = (const float*)d_in[11];
    const float* vLw = (const float*)d_in[12];
    const float* vLb = (const float*)d_in[13];
    const float* beta = (const float*)d_in[14];
    float* out = (float*)d_out;

    k_qkproj<<<dim3(N_ / 64, B_), 256>>>(fL, fU, qLw, qLb, kUw, kUb, qUw, qUb, kLw, kLb);
    k_vconv<<<dim3(N_ / 128, G_, DB), 128>>>(fL, fU, vUw, vUb, vLw, vLb);
    k_zeroS<<<DB * N_ / 256, 256>>>();
    k_expT<<<dim3(N_ / 64, N_ / 256, DB), 256>>>();
    k_scaleVb<<<dim3(N_ / 1024, C_, DB), 256>>>();
    cudaFuncSetAttribute(k_gemm_mma, cudaFuncAttributeMaxDynamicSharedMemorySize, GEMM_SMEM);
    k_gemm_mma<<<dim3(N_ / 128, C_ / 128, DB), 256, GEMM_SMEM>>>(fL, fU, beta, out);
}

// round 12
// speedup vs baseline: 4.4168x; 1.0898x over previous
#include <cuda_runtime.h>
#include <cuda_bf16.h>
#include <cstdint>

#define B_   2
#define C_   256
#define N_   4096
#define R_   8
#define G_   4
#define CG_  64
#define DB   4        // DIRS*B_

// ---------------- scratch ---------------------------------------------------
__device__ float g_q[DB][R_][N_];
__device__ float g_k[DB][R_][N_];
__device__ float g_v[DB][C_][N_];
__device__ float g_S[DB][N_];
__device__ __nv_bfloat16 g_vb[DB][C_][N_];          // v' in bf16 (A operand)
__device__ __nv_bfloat16 g_E[DB][N_][N_];           // Et[m][n] = exp(q_n . k_m)

// ---------------- helpers ----------------------------------------------------
__device__ __forceinline__ uint32_t smem_u32(const void* p) {
    uint32_t a;
    asm("{ .reg .u64 t; cvta.to.shared.u64 t, %1; cvt.u32.u64 %0, t; }" : "=r"(a) : "l"(p));
    return a;
}
#define SWZ(o) ((o) ^ (((o) >> 3) & 0x70))
#define CPA(s, g) asm volatile("cp.async.cg.shared.global [%0], [%1], 16;" :: "r"(s), "l"(g) : "memory")
#define CPC()     asm volatile("cp.async.commit_group;" ::: "memory")
#define CPW(n)    asm volatile("cp.async.wait_group %0;" :: "n"(n) : "memory")

__device__ __forceinline__ void ldsm4(uint32_t* r, uint32_t addr) {
    asm volatile("ldmatrix.sync.aligned.m8n8.x4.shared.b16 {%0,%1,%2,%3}, [%4];"
                 : "=r"(r[0]), "=r"(r[1]), "=r"(r[2]), "=r"(r[3]) : "r"(addr));
}
__device__ __forceinline__ void mma16816(float* d, const uint32_t* a, uint32_t b0, uint32_t b1) {
    asm volatile("mma.sync.aligned.m16n8k16.row.col.f32.bf16.bf16.f32 "
                 "{%0,%1,%2,%3}, {%4,%5,%6,%7}, {%8,%9}, {%0,%1,%2,%3};"
                 : "+f"(d[0]), "+f"(d[1]), "+f"(d[2]), "+f"(d[3])
                 : "r"(a[0]), "r"(a[1]), "r"(a[2]), "r"(a[3]), "r"(b0), "r"(b1));
}

// ---------------- K1: fused low-rank projections (4 c-slices per block) ------
__global__ void k_qkproj(const float* __restrict__ fL, const float* __restrict__ fU,
                         const float* __restrict__ qLw, const float* __restrict__ qLb,
                         const float* __restrict__ kUw, const float* __restrict__ kUb,
                         const float* __restrict__ qUw, const float* __restrict__ qUb,
                         const float* __restrict__ kLw, const float* __restrict__ kLb) {
    __shared__ float sbuf[8448];
    int t = threadIdx.x;
    int n0 = blockIdx.x * 64;
    int b  = blockIdx.y;
    int nl = t & 63, slice = t >> 6;

    for (int i = t; i < R_ * C_; i += 256) {
        sbuf[i] = qLw[i]; sbuf[2048 + i] = kUw[i]; sbuf[4096 + i] = qUw[i]; sbuf[6144 + i] = kLw[i];
    }
    __syncthreads();

    float aQL[R_], aKU[R_], aQU[R_], aKL[R_];
#pragma unroll
    for (int r = 0; r < R_; r++) { aQL[r]=0.f; aKU[r]=0.f; aQU[r]=0.f; aKL[r]=0.f; }
    const float* xl = fL + (size_t)b * C_ * N_ + n0 + nl;
    const float* xu = fU + (size_t)b * C_ * N_ + n0 + nl;
    for (int ci = 0; ci < 64; ci++) {
        int c = slice * 64 + ci;
        float vl = xl[(size_t)c * N_];
        float vu = xu[(size_t)c * N_];
#pragma unroll
        for (int r = 0; r < R_; r++) {
            aQL[r] = fmaf(sbuf[r * 256 + c], vl, aQL[r]);
            aKU[r] = fmaf(sbuf[2048 + r * 256 + c], vu, aKU[r]);
            aQU[r] = fmaf(sbuf[4096 + r * 256 + c], vu, aQU[r]);
            aKL[r] = fmaf(sbuf[6144 + r * 256 + c], vl, aKL[r]);
        }
    }
    __syncthreads();
    {
        float* red = &sbuf[(size_t)(slice * 64 + nl) * 33];
#pragma unroll
        for (int r = 0; r < R_; r++) {
            red[r] = aQL[r]; red[8 + r] = aKU[r]; red[16 + r] = aQU[r]; red[24 + r] = aKL[r];
        }
    }
    __syncthreads();
    {
        int n2 = t & 63, grp = t >> 6;
#pragma unroll
        for (int j = 0; j < R_; j++) {
            int o = grp * 8 + j;
            float s = sbuf[(0 * 64 + n2) * 33 + o] + sbuf[(1 * 64 + n2) * 33 + o]
                    + sbuf[(2 * 64 + n2) * 33 + o] + sbuf[(3 * 64 + n2) * 33 + o];
            int n = n0 + n2;
            if (grp == 0)      g_q[b][j][n]     = s + qLb[j];
            else if (grp == 1) g_k[b][j][n]     = s + kUb[j];
            else if (grp == 2) g_q[2 + b][j][n] = s + qUb[j];
            else               g_k[2 + b][j][n] = s + kLb[j];
        }
    }
}

// ---------------- K2: grouped 1x1 convs -------------------------------------
__global__ void k_vconv(const float* __restrict__ fL, const float* __restrict__ fU,
                        const float* __restrict__ vUw, const float* __restrict__ vUb,
                        const float* __restrict__ vLw, const float* __restrict__ vLb) {
    __shared__ float xs[CG_][128];
    __shared__ float ws[CG_][CG_];
    int t  = threadIdx.x;
    int n0 = blockIdx.x * 128;
    int g  = blockIdx.y;
    int z  = blockIdx.z;
    int dir = z >> 1, b = z & 1;
    const float* x    = dir ? fL  : fU;
    const float* w    = dir ? vLw : vUw;
    const float* bias = dir ? vLb : vUb;
    for (int ci = 0; ci < CG_; ci++)
        xs[ci][t] = x[((size_t)b * C_ + g * CG_ + ci) * N_ + n0 + t];
    for (int i = t; i < CG_ * CG_; i += 128)
        (&ws[0][0])[i] = w[g * CG_ * CG_ + i];
    __syncthreads();
    for (int co = 0; co < CG_; co++) {
        float acc = bias[g * CG_ + co];
#pragma unroll 8
        for (int ci = 0; ci < CG_; ci++)
            acc = fmaf(ws[co][ci], xs[ci][t], acc);
        g_v[z][g * CG_ + co][n0 + t] = acc;
    }
}

// ---------------- K3: Et[m][n]=exp(q_n.k_m) bf16, coalesced, low-reg ---------
// tile 64m x 128n; 8 warps x 8 m-rows; lane -> 4 consecutive n (float4 q regs)
__global__ void __launch_bounds__(256) k_expT() {
    __shared__ float ks[64][9];          // k[m][r], padded
    __shared__ float sacc[8][128];       // per-warp partial column sums
    int t = threadIdx.x, lane = t & 31, w = t >> 5;
    int m0 = blockIdx.x * 64;
    int n0 = blockIdx.y * 128;
    int z  = blockIdx.z;

    for (int i = t; i < 64 * R_; i += 256)
        ks[i >> 3][i & 7] = g_k[z][i & 7][m0 + (i >> 3)];

    float4 qr[R_];                        // 32 regs: q[r] for this lane's 4 n
#pragma unroll
    for (int r = 0; r < R_; r++)
        qr[r] = *(const float4*)&g_q[z][r][n0 + lane * 4];
    __syncthreads();

    float s0 = 0.f, s1 = 0.f, s2 = 0.f, s3 = 0.f;
#pragma unroll
    for (int mi = 0; mi < 8; mi++) {
        int mrow = w * 8 + mi;
        float l0 = 0.f, l1 = 0.f, l2 = 0.f, l3 = 0.f;
#pragma unroll
        for (int r = 0; r < R_; r++) {
            float km = ks[mrow][r];       // broadcast
            l0 = fmaf(qr[r].x, km, l0);
            l1 = fmaf(qr[r].y, km, l1);
            l2 = fmaf(qr[r].z, km, l2);
            l3 = fmaf(qr[r].w, km, l3);
        }
        float e0 = __expf(l0), e1 = __expf(l1), e2 = __expf(l2), e3 = __expf(l3);
        s0 += e0; s1 += e1; s2 += e2; s3 += e3;
        __nv_bfloat162 p0 = __floats2bfloat162_rn(e0, e1);
        __nv_bfloat162 p1 = __floats2bfloat162_rn(e2, e3);
        uint2 u;
        u.x = *(const uint32_t*)&p0;
        u.y = *(const uint32_t*)&p1;
        *(uint2*)&g_E[z][m0 + mrow][n0 + lane * 4] = u;   // warp: 256B contiguous
    }
    sacc[w][lane * 4 + 0] = s0;
    sacc[w][lane * 4 + 1] = s1;
    sacc[w][lane * 4 + 2] = s2;
    sacc[w][lane * 4 + 3] = s3;
    __syncthreads();
    if (t < 128) {
        float tot = sacc[0][t] + sacc[1][t] + sacc[2][t] + sacc[3][t]
                  + sacc[4][t] + sacc[5][t] + sacc[6][t] + sacc[7][t];
        atomicAdd(&g_S[z][n0 + t], tot);
    }
}

__global__ void k_zeroS() {
    ((float*)g_S)[blockIdx.x * 256 + threadIdx.x] = 0.f;
}

// ---------------- K3c: v'[c,n] = v[c,n]/S[n] -> bf16 (vectorized) ------------
__global__ void k_scaleVb() {
    int n4 = (blockIdx.x * 256 + threadIdx.x) * 4;
    int c = blockIdx.y;
    int z = blockIdx.z;
    float4 v = *(const float4*)&g_v[z][c][n4];
    float4 sv = *(const float4*)&g_S[z][n4];
    __nv_bfloat162 o[2];
    o[0] = __floats2bfloat162_rn(v.x / sv.x, v.y / sv.y);
    o[1] = __floats2bfloat162_rn(v.z / sv.z, v.w / sv.w);
    *(uint2*)&g_vb[z][c][n4] = *(const uint2*)o;
}

// ---------------- K4: bf16 mma.sync GEMM  OUT = f + beta * (v' @ Et^T) -------
#define KT 64
#define NKT (N_ / KT)
#define GEMM_SMEM (1024 + 2 * 32768)

__global__ void __launch_bounds__(256, 2) k_gemm_mma(
        const float* __restrict__ fL, const float* __restrict__ fU,
        const float* __restrict__ beta_p, float* __restrict__ out) {
    extern __shared__ char dsm[];
    uint32_t sb0 = smem_u32(dsm);
    uint32_t sb = (sb0 + 1023) & ~1023u;

    int t = threadIdx.x, lane = t & 31, wid = t >> 5;
    int m0 = blockIdx.x * 128, c0 = blockIdx.y * 128, z = blockIdx.z;
    int dir = z >> 1, b = z & 1;
    int wc = wid >> 2, wm = wid & 3;                 // warp tile: 64c x 32m

    const __nv_bfloat16* Ab = &g_vb[z][c0][0];
    const __nv_bfloat16* Bb = &g_E[z][m0][0];

    int row  = t >> 3;
    int colb = (t & 7) * 16;

    float acc[4][4][4];
#pragma unroll
    for (int i = 0; i < 4; i++)
#pragma unroll
        for (int j = 0; j < 4; j++)
#pragma unroll
            for (int q = 0; q < 4; q++) acc[i][j][q] = 0.f;

    uint32_t aRow = (uint32_t)(wc * 64 + (lane & 15));
    uint32_t aKb  = (uint32_t)((lane >> 4) * 16);
    uint32_t bRow = (uint32_t)(wm * 32 + ((lane >> 4) & 1) * 8 + (lane & 7));
    uint32_t bKb  = (uint32_t)(((lane >> 3) & 1) * 16);

    {
        uint32_t base = sb;
        const char* ap = (const char*)Ab + colb;
        const char* bp = (const char*)Bb + colb;
#pragma unroll
        for (int i = 0; i < 4; i++) {
            int r = row + i * 32;
            CPA(base + SWZ(r * 128 + colb), ap + (size_t)r * N_ * 2);
            CPA(base + 16384 + SWZ(r * 128 + colb), bp + (size_t)r * N_ * 2);
        }
        CPC();
    }

    for (int kt = 0; kt < NKT; kt++) {
        if (kt + 1 < NKT) {
            uint32_t base = sb + ((kt + 1) & 1) * 32768;
            size_t kOff = (size_t)(kt + 1) * KT * 2;
            const char* ap = (const char*)Ab + kOff + colb;
            const char* bp = (const char*)Bb + kOff + colb;
#pragma unroll
            for (int i = 0; i < 4; i++) {
                int r = row + i * 32;
                CPA(base + SWZ(r * 128 + colb), ap + (size_t)r * N_ * 2);
                CPA(base + 16384 + SWZ(r * 128 + colb), bp + (size_t)r * N_ * 2);
            }
            CPC();
            CPW(1);
        } else {
            CPW(0);
        }
        __syncthreads();

        uint32_t As = sb + (kt & 1) * 32768;
        uint32_t Bs = As + 16384;
#pragma unroll
        for (int kk = 0; kk < 4; kk++) {
            uint32_t a[4][4], brg[2][4];
#pragma unroll
            for (int i = 0; i < 4; i++)
                ldsm4(a[i], As + SWZ((aRow + i * 16) * 128 + kk * 32 + aKb));
#pragma unroll
            for (int jj = 0; jj < 2; jj++)
                ldsm4(brg[jj], Bs + SWZ((bRow + jj * 16) * 128 + kk * 32 + bKb));
#pragma unroll
            for (int i = 0; i < 4; i++)
#pragma unroll
                for (int j = 0; j < 4; j++)
                    mma16816(acc[i][j], a[i], brg[j >> 1][(j & 1) * 2], brg[j >> 1][(j & 1) * 2 + 1]);
        }
        __syncthreads();
    }

    float beta = *beta_p;
    const float* fsrc = dir ? fU : fL;
    float* osrc = out + (size_t)dir * B_ * C_ * N_;
#pragma unroll
    for (int i = 0; i < 4; i++) {
        int cr = c0 + wc * 64 + i * 16 + (lane >> 2);
#pragma unroll
        for (int j = 0; j < 4; j++) {
            int mc = m0 + wm * 32 + j * 8 + (lane & 3) * 2;
            size_t i0 = ((size_t)b * C_ + cr) * N_ + mc;
            size_t i1 = i0 + 8 * (size_t)N_;
            float2 f0 = *(const float2*)&fsrc[i0];
            float2 f1 = *(const float2*)&fsrc[i1];
            float2 d0, d1;
            d0.x = f0.x + beta * acc[i][j][0];
            d0.y = f0.y + beta * acc[i][j][1];
            d1.x = f1.x + beta * acc[i][j][2];
            d1.y = f1.y + beta * acc[i][j][3];
            *(float2*)&osrc[i0] = d0;
            *(float2*)&osrc[i1] = d1;
        }
    }
}

// ---------------- launch -----------------------------------------------------
extern "C" void kernel_launch(void* const* d_in, const int* in_sizes, int n_in,
                              void* d_out, int out_size) {
    const float* fL  = (const float*)d_in[0];
    const float* fU  = (const float*)d_in[1];
    const float* qLw = (const float*)d_in[2];
    const float* qLb = (const float*)d_in[3];
    const float* kUw = (const float*)d_in[4];
    const float* kUb = (const float*)d_in[5];
    const float* vUw = (const float*)d_in[6];
    const float* vUb = (const float*)d_in[7];
    const float* qUw = (const float*)d_in[8];
    const float* qUb = (const float*)d_in[9];
    const float* kLw = (const float*)d_in[10];
    const float* kLb = (const float*)d_in[11];
    const float* vLw = (const float*)d_in[12];
    const float* vLb = (const float*)d_in[13];
    const float* beta = (const float*)d_in[14];
    float* out = (float*)d_out;

    k_qkproj<<<dim3(N_ / 64, B_), 256>>>(fL, fU, qLw, qLb, kUw, kUb, qUw, qUb, kLw, kLb);
    k_vconv<<<dim3(N_ / 128, G_, DB), 128>>>(fL, fU, vUw, vUb, vLw, vLb);
    k_zeroS<<<DB * N_ / 256, 256>>>();
    k_expT<<<dim3(N_ / 64, N_ / 128, DB), 256>>>();
    k_scaleVb<<<dim3(N_ / 1024, C_, DB), 256>>>();
    cudaFuncSetAttribute(k_gemm_mma, cudaFuncAttributeMaxDynamicSharedMemorySize, GEMM_SMEM);
    k_gemm_mma<<<dim3(N_ / 128, C_ / 128, DB), 256, GEMM_SMEM>>>(fL, fU, beta, out);
}

// round 13
// speedup vs baseline: 4.4498x; 1.0075x over previous
#include <cuda_runtime.h>
#include <cuda_bf16.h>
#include <cstdint>

#define B_   2
#define C_   256
#define N_   4096
#define R_   8
#define G_   4
#define CG_  64
#define DB   4        // DIRS*B_

// ---------------- scratch ---------------------------------------------------
__device__ float g_q[DB][R_][N_];
__device__ float g_k[DB][R_][N_];
__device__ float g_v[DB][C_][N_];
__device__ float g_S[DB][N_];
__device__ __nv_bfloat16 g_vb[DB][C_][N_];          // v' in bf16 (A operand)
__device__ __nv_bfloat16 g_E[DB][N_][N_];           // Et[m][n] = exp(q_n . k_m)

// ---------------- helpers ----------------------------------------------------
__device__ __forceinline__ uint32_t smem_u32(const void* p) {
    uint32_t a;
    asm("{ .reg .u64 t; cvta.to.shared.u64 t, %1; cvt.u32.u64 %0, t; }" : "=r"(a) : "l"(p));
    return a;
}
#define SWZ(o) ((o) ^ (((o) >> 3) & 0x70))
#define CPA(s, g) asm volatile("cp.async.cg.shared.global [%0], [%1], 16;" :: "r"(s), "l"(g) : "memory")
#define CPC()     asm volatile("cp.async.commit_group;" ::: "memory")
#define CPW(n)    asm volatile("cp.async.wait_group %0;" :: "n"(n) : "memory")

__device__ __forceinline__ void ldsm4(uint32_t* r, uint32_t addr) {
    asm volatile("ldmatrix.sync.aligned.m8n8.x4.shared.b16 {%0,%1,%2,%3}, [%4];"
                 : "=r"(r[0]), "=r"(r[1]), "=r"(r[2]), "=r"(r[3]) : "r"(addr));
}
__device__ __forceinline__ void mma16816(float* d, const uint32_t* a, uint32_t b0, uint32_t b1) {
    asm volatile("mma.sync.aligned.m16n8k16.row.col.f32.bf16.bf16.f32 "
                 "{%0,%1,%2,%3}, {%4,%5,%6,%7}, {%8,%9}, {%0,%1,%2,%3};"
                 : "+f"(d[0]), "+f"(d[1]), "+f"(d[2]), "+f"(d[3])
                 : "r"(a[0]), "r"(a[1]), "r"(a[2]), "r"(a[3]), "r"(b0), "r"(b1));
}

// ---------------- K1: fused low-rank projections (+ S zeroing folded in) -----
__global__ void k_qkproj(const float* __restrict__ fL, const float* __restrict__ fU,
                         const float* __restrict__ qLw, const float* __restrict__ qLb,
                         const float* __restrict__ kUw, const float* __restrict__ kUb,
                         const float* __restrict__ qUw, const float* __restrict__ qUb,
                         const float* __restrict__ kLw, const float* __restrict__ kLb) {
    __shared__ float sbuf[8448];
    int t = threadIdx.x;
    int n0 = blockIdx.x * 64;
    int b  = blockIdx.y;
    int nl = t & 63, slice = t >> 6;

    if (t < 64) {                 // fold k_zeroS: each (n0,b) block zeroes its S slots
        g_S[b][n0 + t] = 0.f;
        g_S[2 + b][n0 + t] = 0.f;
    }

    for (int i = t; i < R_ * C_; i += 256) {
        sbuf[i] = qLw[i]; sbuf[2048 + i] = kUw[i]; sbuf[4096 + i] = qUw[i]; sbuf[6144 + i] = kLw[i];
    }
    __syncthreads();

    float aQL[R_], aKU[R_], aQU[R_], aKL[R_];
#pragma unroll
    for (int r = 0; r < R_; r++) { aQL[r]=0.f; aKU[r]=0.f; aQU[r]=0.f; aKL[r]=0.f; }
    const float* xl = fL + (size_t)b * C_ * N_ + n0 + nl;
    const float* xu = fU + (size_t)b * C_ * N_ + n0 + nl;
    for (int ci = 0; ci < 64; ci++) {
        int c = slice * 64 + ci;
        float vl = xl[(size_t)c * N_];
        float vu = xu[(size_t)c * N_];
#pragma unroll
        for (int r = 0; r < R_; r++) {
            aQL[r] = fmaf(sbuf[r * 256 + c], vl, aQL[r]);
            aKU[r] = fmaf(sbuf[2048 + r * 256 + c], vu, aKU[r]);
            aQU[r] = fmaf(sbuf[4096 + r * 256 + c], vu, aQU[r]);
            aKL[r] = fmaf(sbuf[6144 + r * 256 + c], vl, aKL[r]);
        }
    }
    __syncthreads();
    {
        float* red = &sbuf[(size_t)(slice * 64 + nl) * 33];
#pragma unroll
        for (int r = 0; r < R_; r++) {
            red[r] = aQL[r]; red[8 + r] = aKU[r]; red[16 + r] = aQU[r]; red[24 + r] = aKL[r];
        }
    }
    __syncthreads();
    {
        int n2 = t & 63, grp = t >> 6;
#pragma unroll
        for (int j = 0; j < R_; j++) {
            int o = grp * 8 + j;
            float s = sbuf[(0 * 64 + n2) * 33 + o] + sbuf[(1 * 64 + n2) * 33 + o]
                    + sbuf[(2 * 64 + n2) * 33 + o] + sbuf[(3 * 64 + n2) * 33 + o];
            int n = n0 + n2;
            if (grp == 0)      g_q[b][j][n]     = s + qLb[j];
            else if (grp == 1) g_k[b][j][n]     = s + kUb[j];
            else if (grp == 2) g_q[2 + b][j][n] = s + qUb[j];
            else               g_k[2 + b][j][n] = s + kLb[j];
        }
    }
}

// ---------------- K2: grouped 1x1 convs -------------------------------------
__global__ void k_vconv(const float* __restrict__ fL, const float* __restrict__ fU,
                        const float* __restrict__ vUw, const float* __restrict__ vUb,
                        const float* __restrict__ vLw, const float* __restrict__ vLb) {
    __shared__ float xs[CG_][128];
    __shared__ float ws[CG_][CG_];
    int t  = threadIdx.x;
    int n0 = blockIdx.x * 128;
    int g  = blockIdx.y;
    int z  = blockIdx.z;
    int dir = z >> 1, b = z & 1;
    const float* x    = dir ? fL  : fU;
    const float* w    = dir ? vLw : vUw;
    const float* bias = dir ? vLb : vUb;
    for (int ci = 0; ci < CG_; ci++)
        xs[ci][t] = x[((size_t)b * C_ + g * CG_ + ci) * N_ + n0 + t];
    for (int i = t; i < CG_ * CG_; i += 128)
        (&ws[0][0])[i] = w[g * CG_ * CG_ + i];
    __syncthreads();
    for (int co = 0; co < CG_; co++) {
        float acc = bias[g * CG_ + co];
#pragma unroll 8
        for (int ci = 0; ci < CG_; ci++)
            acc = fmaf(ws[co][ci], xs[ci][t], acc);
        g_v[z][g * CG_ + co][n0 + t] = acc;
    }
}

// ---------------- K3: Et[m][n]=exp(q_n.k_m) bf16, coalesced, low-reg ---------
__global__ void __launch_bounds__(256) k_expT() {
    __shared__ float ks[64][9];
    __shared__ float sacc[8][128];
    int t = threadIdx.x, lane = t & 31, w = t >> 5;
    int m0 = blockIdx.x * 64;
    int n0 = blockIdx.y * 128;
    int z  = blockIdx.z;

    for (int i = t; i < 64 * R_; i += 256)
        ks[i >> 3][i & 7] = g_k[z][i & 7][m0 + (i >> 3)];

    float4 qr[R_];
#pragma unroll
    for (int r = 0; r < R_; r++)
        qr[r] = *(const float4*)&g_q[z][r][n0 + lane * 4];
    __syncthreads();

    float s0 = 0.f, s1 = 0.f, s2 = 0.f, s3 = 0.f;
#pragma unroll
    for (int mi = 0; mi < 8; mi++) {
        int mrow = w * 8 + mi;
        float l0 = 0.f, l1 = 0.f, l2 = 0.f, l3 = 0.f;
#pragma unroll
        for (int r = 0; r < R_; r++) {
            float km = ks[mrow][r];
            l0 = fmaf(qr[r].x, km, l0);
            l1 = fmaf(qr[r].y, km, l1);
            l2 = fmaf(qr[r].z, km, l2);
            l3 = fmaf(qr[r].w, km, l3);
        }
        float e0 = __expf(l0), e1 = __expf(l1), e2 = __expf(l2), e3 = __expf(l3);
        s0 += e0; s1 += e1; s2 += e2; s3 += e3;
        __nv_bfloat162 p0 = __floats2bfloat162_rn(e0, e1);
        __nv_bfloat162 p1 = __floats2bfloat162_rn(e2, e3);
        uint2 u;
        u.x = *(const uint32_t*)&p0;
        u.y = *(const uint32_t*)&p1;
        *(uint2*)&g_E[z][m0 + mrow][n0 + lane * 4] = u;
    }
    sacc[w][lane * 4 + 0] = s0;
    sacc[w][lane * 4 + 1] = s1;
    sacc[w][lane * 4 + 2] = s2;
    sacc[w][lane * 4 + 3] = s3;
    __syncthreads();
    if (t < 128) {
        float tot = sacc[0][t] + sacc[1][t] + sacc[2][t] + sacc[3][t]
                  + sacc[4][t] + sacc[5][t] + sacc[6][t] + sacc[7][t];
        atomicAdd(&g_S[z][n0 + t], tot);
    }
}

// ---------------- K3c: v'[c,n] = v[c,n]/S[n] -> bf16 -------------------------
__global__ void k_scaleVb() {
    int n4 = (blockIdx.x * 256 + threadIdx.x) * 4;
    int c = blockIdx.y;
    int z = blockIdx.z;
    float4 v = *(const float4*)&g_v[z][c][n4];
    float4 sv = *(const float4*)&g_S[z][n4];
    __nv_bfloat162 o[2];
    o[0] = __floats2bfloat162_rn(v.x / sv.x, v.y / sv.y);
    o[1] = __floats2bfloat162_rn(v.z / sv.z, v.w / sv.w);
    *(uint2*)&g_vb[z][c][n4] = *(const uint2*)o;
}

// ---------------- K4: bf16 mma.sync GEMM, 3-stage pipeline, 1 sync/iter ------
#define KT 64
#define NKT (N_ / KT)
#define STG 3
#define STG_BYTES 32768
#define GEMM_SMEM (1024 + STG * STG_BYTES)

__global__ void __launch_bounds__(256, 2) k_gemm_mma(
        const float* __restrict__ fL, const float* __restrict__ fU,
        const float* __restrict__ beta_p, float* __restrict__ out) {
    extern __shared__ char dsm[];
    uint32_t sb0 = smem_u32(dsm);
    uint32_t sb = (sb0 + 1023) & ~1023u;

    int t = threadIdx.x, lane = t & 31, wid = t >> 5;
    int m0 = blockIdx.x * 128, c0 = blockIdx.y * 128, z = blockIdx.z;
    int dir = z >> 1, b = z & 1;
    int wc = wid >> 2, wm = wid & 3;                 // warp tile: 64c x 32m

    const __nv_bfloat16* Ab = &g_vb[z][c0][0];
    const __nv_bfloat16* Bb = &g_E[z][m0][0];

    int row  = t >> 3;
    int colb = (t & 7) * 16;

    float acc[4][4][4];
#pragma unroll
    for (int i = 0; i < 4; i++)
#pragma unroll
        for (int j = 0; j < 4; j++)
#pragma unroll
            for (int q = 0; q < 4; q++) acc[i][j][q] = 0.f;

    uint32_t aRow = (uint32_t)(wc * 64 + (lane & 15));
    uint32_t aKb  = (uint32_t)((lane >> 4) * 16);
    uint32_t bRow = (uint32_t)(wm * 32 + ((lane >> 4) & 1) * 8 + (lane & 7));
    uint32_t bKb  = (uint32_t)(((lane >> 3) & 1) * 16);

    // prologue: issue stages 0 and 1
#pragma unroll
    for (int pk = 0; pk < 2; pk++) {
        uint32_t base = sb + pk * STG_BYTES;
        size_t kOff = (size_t)pk * KT * 2;
        const char* ap = (const char*)Ab + kOff + colb;
        const char* bp = (const char*)Bb + kOff + colb;
#pragma unroll
        for (int i = 0; i < 4; i++) {
            int r = row + i * 32;
            CPA(base + SWZ(r * 128 + colb), ap + (size_t)r * N_ * 2);
            CPA(base + 16384 + SWZ(r * 128 + colb), bp + (size_t)r * N_ * 2);
        }
        CPC();
    }

    int buf = 0;
    for (int kt = 0; kt < NKT; kt++) {
        CPW(1);                       // stage kt resident (only kt+1 may pend)
        __syncthreads();              // also fences prior iteration's reads

        if (kt + 2 < NKT) {           // issue stage kt+2 into the just-freed buffer
            int nbuf = buf + 2; if (nbuf >= STG) nbuf -= STG;
            uint32_t base = sb + nbuf * STG_BYTES;
            size_t kOff = (size_t)(kt + 2) * KT * 2;
            const char* ap = (const char*)Ab + kOff + colb;
            const char* bp = (const char*)Bb + kOff + colb;
#pragma unroll
            for (int i = 0; i < 4; i++) {
                int r = row + i * 32;
                CPA(base + SWZ(r * 128 + colb), ap + (size_t)r * N_ * 2);
                CPA(base + 16384 + SWZ(r * 128 + colb), bp + (size_t)r * N_ * 2);
            }
            CPC();
        }

        uint32_t As = sb + buf * STG_BYTES;
        uint32_t Bs = As + 16384;
#pragma unroll
        for (int kk = 0; kk < 4; kk++) {
            uint32_t a[4][4], brg[2][4];
#pragma unroll
            for (int i = 0; i < 4; i++)
                ldsm4(a[i], As + SWZ((aRow + i * 16) * 128 + kk * 32 + aKb));
#pragma unroll
            for (int jj = 0; jj < 2; jj++)
                ldsm4(brg[jj], Bs + SWZ((bRow + jj * 16) * 128 + kk * 32 + bKb));
#pragma unroll
            for (int i = 0; i < 4; i++)
#pragma unroll
                for (int j = 0; j < 4; j++)
                    mma16816(acc[i][j], a[i], brg[j >> 1][(j & 1) * 2], brg[j >> 1][(j & 1) * 2 + 1]);
        }
        buf++; if (buf >= STG) buf -= STG;
    }

    float beta = *beta_p;
    const float* fsrc = dir ? fU : fL;
    float* osrc = out + (size_t)dir * B_ * C_ * N_;
#pragma unroll
    for (int i = 0; i < 4; i++) {
        int cr = c0 + wc * 64 + i * 16 + (lane >> 2);
#pragma unroll
        for (int j = 0; j < 4; j++) {
            int mc = m0 + wm * 32 + j * 8 + (lane & 3) * 2;
            size_t i0 = ((size_t)b * C_ + cr) * N_ + mc;
            size_t i1 = i0 + 8 * (size_t)N_;
            float2 f0 = *(const float2*)&fsrc[i0];
            float2 f1 = *(const float2*)&fsrc[i1];
            float2 d0, d1;
            d0.x = f0.x + beta * acc[i][j][0];
            d0.y = f0.y + beta * acc[i][j][1];
            d1.x = f1.x + beta * acc[i][j][2];
            d1.y = f1.y + beta * acc[i][j][3];
            *(float2*)&osrc[i0] = d0;
            *(float2*)&osrc[i1] = d1;
        }
    }
}

// ---------------- launch -----------------------------------------------------
extern "C" void kernel_launch(void* const* d_in, const int* in_sizes, int n_in,
                              void* d_out, int out_size) {
    const float* fL  = (const float*)d_in[0];
    const float* fU  = (const float*)d_in[1];
    const float* qLw = (const float*)d_in[2];
    const float* qLb = (const float*)d_in[3];
    const float* kUw = (const float*)d_in[4];
    const float* kUb = (const float*)d_in[5];
    const float* vUw = (const float*)d_in[6];
    const float* vUb = (const float*)d_in[7];
    const float* qUw = (const float*)d_in[8];
    const float* qUb = (const float*)d_in[9];
    const float* kLw = (const float*)d_in[10];
    const float* kLb = (const float*)d_in[11];
    const float* vLw = (const float*)d_in[12];
    const float* vLb = (const float*)d_in[13];
    const float* beta = (const float*)d_in[14];
    float* out = (float*)d_out;

    k_qkproj<<<dim3(N_ / 64, B_), 256>>>(fL, fU, qLw, qLb, kUw, kUb, qUw, qUb, kLw, kLb);
    k_vconv<<<dim3(N_ / 128, G_, DB), 128>>>(fL, fU, vUw, vUb, vLw, vLb);
    k_expT<<<dim3(N_ / 64, N_ / 128, DB), 256>>>();
    k_scaleVb<<<dim3(N_ / 1024, C_, DB), 256>>>();
    cudaFuncSetAttribute(k_gemm_mma, cudaFuncAttributeMaxDynamicSharedMemorySize, GEMM_SMEM);
    k_gemm_mma<<<dim3(N_ / 128, C_ / 128, DB), 256, GEMM_SMEM>>>(fL, fU, beta, out);
}